// round 16
// baseline (speedup 1.0000x reference)
#include <cuda_runtime.h>

// N = 4096, B = 8192. out[b,n] = x[b,n] * kmat[n,n].
// Base = R13 (best measured: kernel 37.9us, total 43.5us, DRAM 72%).
// R15 single knob: __stcs -> __stwt on out. Rationale: stcs leaves ~50MB
// of dirty L2 lines draining AFTER kernel end; under graph replay that
// drain collides with the next replay's read burst (r/w turnaround).
// Write-through lands writes in-window, smoothly interleaved with reads.
#define DIAG_N 4096
#define BATCH_B 8192
#define ROW_F4 (DIAG_N / 4)     // 1024 float4 per row
#define THREADS 256
#define F4_PER_THREAD 2         // proven MLP sweet spot
#define GATHER_BLOCKS 16        // 16 * 256 = 4096 diag elements
#define SCALE_BLOCKS ((BATCH_B * ROW_F4) / (THREADS * F4_PER_THREAD)) // 16384

__device__ float4 g_diag4[ROW_F4];
__device__ int    g_flag;   // zero-initialized; monotone across graph replays

__global__ void __launch_bounds__(THREADS)
fused_diag_scale_kernel(const float*  __restrict__ kmat,
                        const float4* __restrict__ x,
                        float4*       __restrict__ out) {
    if (blockIdx.x < GATHER_BLOCKS) {
        // ---- Producer: gather diagonal (strided) into compact 16 KB array.
        int i = blockIdx.x * THREADS + threadIdx.x;
        reinterpret_cast<float*>(g_diag4)[i] =
            __ldg(&kmat[(size_t)i * (DIAG_N + 1)]);
        __threadfence();            // release: diag writes visible at L2
        __syncthreads();            // all 256 writes+fences done
        if (threadIdx.x == 0) atomicAdd(&g_flag, 1);
        return;
    }

    // ---- Consumer: ONE thread polls the flag, barrier fences the rest.
    // (All-thread polling serializes an L2 slice — proven in R12.)
    // Replays >= 2: flag already >= 16, single poll. Deadlock-free: gather
    // blocks hold the lowest indices -> guaranteed wave-1 residency.
    if (threadIdx.x == 0) {
        volatile int* f = &g_flag;  // L1-bypassing strong load
        while (*f < GATHER_BLOCKS) { __nanosleep(64); }
    }
    __syncthreads();                // orders diag reads after the spin

    const int t = threadIdx.x;
    const size_t base =
        (size_t)(blockIdx.x - GATHER_BLOCKS) * (THREADS * F4_PER_THREAD);
    const int dbase = (int)(base & (ROW_F4 - 1));   // 0 or 512

    // x: evict-first streaming loads (touched exactly once).
    float4 v0 = __ldcs(&x[base + t]);
    float4 v1 = __ldcs(&x[base + t + THREADS]);

    // Diag: 16 KB compact array, L2- then L1-resident per SM.
    float4 d0 = g_diag4[dbase + t];
    float4 d1 = g_diag4[dbase + t + THREADS];

    v0.x *= d0.x; v0.y *= d0.y; v0.z *= d0.z; v0.w *= d0.w;
    v1.x *= d1.x; v1.y *= d1.y; v1.z *= d1.z; v1.w *= d1.w;

    // out: write-through stores — no post-kernel dirty drain to collide
    // with the next replay's read burst.
    __stwt(&out[base + t],           v0);
    __stwt(&out[base + t + THREADS], v1);
}

extern "C" void kernel_launch(void* const* d_in, const int* in_sizes, int n_in,
                              void* d_out, int out_size) {
    const float* x    = (const float*)d_in[0];   // [B, N] fp32
    const float* kmat = (const float*)d_in[1];   // [N, N] fp32
    float* out        = (float*)d_out;           // [B, N] fp32

    fused_diag_scale_kernel<<<GATHER_BLOCKS + SCALE_BLOCKS, THREADS>>>(
        kmat, (const float4*)x, (float4*)out);
}

// round 17
// speedup vs baseline: 1.0368x; 1.0368x over previous
#include <cuda_runtime.h>

// N = 4096, B = 8192. out[b,n] = x[b,n] * kmat[n,n].
// Base = R13 (best measured: kernel 37.9us, total 43.5us, DRAM 72%).
// R15 single knob: __stcs -> __stwt on out. Rationale: stcs leaves ~50MB
// of dirty L2 lines draining AFTER kernel end; under graph replay that
// drain collides with the next replay's read burst (r/w turnaround).
// Write-through lands writes in-window, smoothly interleaved with reads.
#define DIAG_N 4096
#define BATCH_B 8192
#define ROW_F4 (DIAG_N / 4)     // 1024 float4 per row
#define THREADS 256
#define F4_PER_THREAD 2         // proven MLP sweet spot
#define GATHER_BLOCKS 16        // 16 * 256 = 4096 diag elements
#define SCALE_BLOCKS ((BATCH_B * ROW_F4) / (THREADS * F4_PER_THREAD)) // 16384

__device__ float4 g_diag4[ROW_F4];
__device__ int    g_flag;   // zero-initialized; monotone across graph replays

__global__ void __launch_bounds__(THREADS)
fused_diag_scale_kernel(const float*  __restrict__ kmat,
                        const float4* __restrict__ x,
                        float4*       __restrict__ out) {
    if (blockIdx.x < GATHER_BLOCKS) {
        // ---- Producer: gather diagonal (strided) into compact 16 KB array.
        int i = blockIdx.x * THREADS + threadIdx.x;
        reinterpret_cast<float*>(g_diag4)[i] =
            __ldg(&kmat[(size_t)i * (DIAG_N + 1)]);
        __threadfence();            // release: diag writes visible at L2
        __syncthreads();            // all 256 writes+fences done
        if (threadIdx.x == 0) atomicAdd(&g_flag, 1);
        return;
    }

    // ---- Consumer: ONE thread polls the flag, barrier fences the rest.
    // (All-thread polling serializes an L2 slice — proven in R12.)
    // Replays >= 2: flag already >= 16, single poll. Deadlock-free: gather
    // blocks hold the lowest indices -> guaranteed wave-1 residency.
    if (threadIdx.x == 0) {
        volatile int* f = &g_flag;  // L1-bypassing strong load
        while (*f < GATHER_BLOCKS) { __nanosleep(64); }
    }
    __syncthreads();                // orders diag reads after the spin

    const int t = threadIdx.x;
    const size_t base =
        (size_t)(blockIdx.x - GATHER_BLOCKS) * (THREADS * F4_PER_THREAD);
    const int dbase = (int)(base & (ROW_F4 - 1));   // 0 or 512

    // x: evict-first streaming loads (touched exactly once).
    float4 v0 = __ldcs(&x[base + t]);
    float4 v1 = __ldcs(&x[base + t + THREADS]);

    // Diag: 16 KB compact array, L2- then L1-resident per SM.
    float4 d0 = g_diag4[dbase + t];
    float4 d1 = g_diag4[dbase + t + THREADS];

    v0.x *= d0.x; v0.y *= d0.y; v0.z *= d0.z; v0.w *= d0.w;
    v1.x *= d1.x; v1.y *= d1.y; v1.z *= d1.z; v1.w *= d1.w;

    // out: write-through stores — no post-kernel dirty drain to collide
    // with the next replay's read burst.
    __stwt(&out[base + t],           v0);
    __stwt(&out[base + t + THREADS], v1);
}

extern "C" void kernel_launch(void* const* d_in, const int* in_sizes, int n_in,
                              void* d_out, int out_size) {
    const float* x    = (const float*)d_in[0];   // [B, N] fp32
    const float* kmat = (const float*)d_in[1];   // [N, N] fp32
    float* out        = (float*)d_out;           // [B, N] fp32

    fused_diag_scale_kernel<<<GATHER_BLOCKS + SCALE_BLOCKS, THREADS>>>(
        kmat, (const float4*)x, (float4*)out);
}